// round 4
// baseline (speedup 1.0000x reference)
#include <cuda_runtime.h>

// GAFM reduced form (softmax over singleton axis == 1 -> attention MLP dead):
//   hop0: agg0[j] = FM(renorm(E[nbr0[j,:]])) + renorm(E[node_ids0[j]])
//   hop1: items   = FM(agg0[nbr1_idx[i,:]]) + renorm(E[item_ids[i]])
//         logit_i = sigmoid(<renorm(U[u[i]]), items>)
//
// hop0 is DRAM-bound at ~500 MB (repeat gathers thrash L2: 256 MB table vs
// 126 MB L2). Two index-range passes shrink the per-pass row footprint to
// ~112 MB so repeats hit L2; partials stream through scratch with .cs hints.

constexpr int K    = 64;
constexpr int B    = 2048;
constexpr int DEG  = 32;
constexpr int N0   = B * DEG;        // 65536
constexpr int MID  = 500000;         // split of the 1M-entity table
constexpr int NENT = 1000000;

__device__ float  g_agg0[(size_t)N0 * K];    // 16 MB hop-0 aggregates
__device__ float4 g_part[(size_t)N0 * 32];   // 32 MB (s0,s1,q0,q1) per node-lane

__device__ __forceinline__ float warp_sum(float v) {
#pragma unroll
    for (int o = 16; o; o >>= 1) v += __shfl_xor_sync(0xffffffffu, v, o);
    return v;
}

// ---------------- hop 0, range pass: one warp per frontier node ----------------
// Lane l owns dims {2l, 2l+1}. Only neighbors with LO <= idx < HI are loaded;
// out-of-range neighbors contribute exact zeros (ss=0 -> sc=1 -> x=0).
template <int LO, int HI, bool FIRST, bool LAST>
__global__ void __launch_bounds__(256) hop0_pass(
    const float* __restrict__ ent,
    const int*   __restrict__ node_ids0,
    const int*   __restrict__ nbr0)
{
    int warp = (blockIdx.x * blockDim.x + threadIdx.x) >> 5;
    int lane = threadIdx.x & 31;
    if (warp >= N0) return;

    int myn = __ldg(nbr0 + warp * DEG + lane);   // lane i holds neighbor i

    float s0, s1, q0, q1;
    if (FIRST) {
        s0 = s1 = q0 = q1 = 0.f;
    } else {
        float4 p = __ldcs(&g_part[(size_t)warp * 32 + lane]);  // streaming load
        s0 = p.x; s1 = p.y; q0 = p.z; q1 = p.w;
    }

#pragma unroll
    for (int base = 0; base < DEG; base += 8) {
        float2 v[8];
#pragma unroll
        for (int g = 0; g < 8; ++g) {
            int idx = __shfl_sync(0xffffffffu, myn, base + g);
            v[g] = make_float2(0.f, 0.f);
            if (idx >= LO && idx < HI)
                v[g] = __ldg((const float2*)(ent + (size_t)idx * K) + lane);
        }
#pragma unroll
        for (int g = 0; g < 8; ++g) {
            float ss = warp_sum(v[g].x * v[g].x + v[g].y * v[g].y);
            float sc = ss > 1.f ? rsqrtf(ss) : 1.f;   // min(1, 1/||row||)
            float x0 = v[g].x * sc, x1 = v[g].y * sc;
            s0 += x0; s1 += x1;
            q0 += x0 * x0; q1 += x1 * x1;
        }
    }

    if (LAST) {
        int nid = __ldg(node_ids0 + warp);
        float2 t = __ldg((const float2*)(ent + (size_t)nid * K) + lane);
        float ts  = warp_sum(t.x * t.x + t.y * t.y);
        float tsc = ts > 1.f ? rsqrtf(ts) : 1.f;
        float2 o;
        o.x = s0 * s0 - q0 + t.x * tsc;
        o.y = s1 * s1 - q1 + t.y * tsc;
        __stcs((float2*)(g_agg0 + (size_t)warp * K) + lane, o);
    } else {
        __stcs(&g_part[(size_t)warp * 32 + lane], make_float4(s0, s1, q0, q1));
    }
}

// ---------------- hop 1: one block (4 warps) per batch item ----------------
__global__ void __launch_bounds__(128) hop1_kernel(
    const float* __restrict__ ent,
    const float* __restrict__ uemb,
    const int*   __restrict__ u,
    const int*   __restrict__ item_ids,
    const int*   __restrict__ nbr1,
    float*       __restrict__ out)
{
    __shared__ float4 part[4][32];

    int item = blockIdx.x;
    int w    = threadIdx.x >> 5;
    int lane = threadIdx.x & 31;

    int myn = 0;
    if (lane < 8) myn = __ldg(nbr1 + item * DEG + w * 8 + lane);

    float2 t = make_float2(0.f, 0.f), uv = make_float2(0.f, 0.f);
    if (w == 0) {
        int it = __ldg(item_ids + item);
        int uu = __ldg(u + item);
        t  = __ldg((const float2*)(ent  + (size_t)it * K) + lane);
        uv = __ldg((const float2*)(uemb + (size_t)uu * K) + lane);
    }

    float2 v[8];
#pragma unroll
    for (int g = 0; g < 8; ++g) {
        int idx = __shfl_sync(0xffffffffu, myn, g);
        v[g] = ((const float2*)(g_agg0 + (size_t)idx * K))[lane];
    }
    float s0 = 0.f, s1 = 0.f, q0 = 0.f, q1 = 0.f;
#pragma unroll
    for (int g = 0; g < 8; ++g) {
        s0 += v[g].x; s1 += v[g].y;
        q0 += v[g].x * v[g].x; q1 += v[g].y * v[g].y;
    }
    part[w][lane] = make_float4(s0, s1, q0, q1);
    __syncthreads();

    if (w == 0) {
        float4 a = part[0][lane], b = part[1][lane],
               c = part[2][lane], d = part[3][lane];
        float S0 = a.x + b.x + c.x + d.x;
        float S1 = a.y + b.y + c.y + d.y;
        float Q0 = a.z + b.z + c.z + d.z;
        float Q1 = a.w + b.w + c.w + d.w;

        float ts  = warp_sum(t.x * t.x + t.y * t.y);
        float tsc = ts > 1.f ? rsqrtf(ts) : 1.f;
        float i0 = S0 * S0 - Q0 + t.x * tsc;
        float i1 = S1 * S1 - Q1 + t.y * tsc;

        float us  = warp_sum(uv.x * uv.x + uv.y * uv.y);
        float usc = us > 1.f ? rsqrtf(us) : 1.f;

        float dot = warp_sum(uv.x * usc * i0 + uv.y * usc * i1);
        if (lane == 0) out[item] = 1.f / (1.f + expf(-dot));
    }
}

extern "C" void kernel_launch(void* const* d_in, const int* in_sizes, int n_in,
                              void* d_out, int out_size)
{
    const float* ent       = (const float*)d_in[0];
    const float* uemb      = (const float*)d_in[1];
    // d_in[2..5]: Wa, ba, Wh, bh — dead
    const int*   u         = (const int*)d_in[6];
    const int*   item_ids  = (const int*)d_in[7];
    const int*   nbr1      = (const int*)d_in[8];
    const int*   node_ids0 = (const int*)d_in[9];
    const int*   nbr0      = (const int*)d_in[10];
    float*       out       = (float*)d_out;

    hop0_pass<0,   MID,  true,  false><<<N0 / 8, 256>>>(ent, node_ids0, nbr0);
    hop0_pass<MID, NENT, false, true ><<<N0 / 8, 256>>>(ent, node_ids0, nbr0);
    hop1_kernel<<<B, 128>>>(ent, uemb, u, item_ids, nbr1, out);
}

// round 5
// speedup vs baseline: 1.9531x; 1.9531x over previous
#include <cuda_runtime.h>

// GAFM reduced form (softmax over singleton axis == 1 -> attention MLP dead):
//   hop0: agg0[j] = FM(renorm(E[nbr0[j,:]])) + renorm(E[node_ids0[j]])
//   hop1: items   = FM(agg0[nbr1_idx[i,:]]) + renorm(E[item_ids[i]])
//         logit_i = sigmoid(<renorm(U[u[i]]), items>)
//
// hop0 is ISSUE-bound (R4 profile: issue 89%, fma 47%, alu 41%, DRAM 28%).
// This version processes 2 nodes per warp in 16-lane groups (float4/lane):
// one LDG.128 + one 4-stage butterfly serve a neighbor of BOTH nodes,
// cutting warp-instructions per node-neighbor from ~21 to ~14.5.

constexpr int K    = 64;
constexpr int B    = 2048;
constexpr int DEG  = 32;
constexpr int N0   = B * DEG;   // 65536

__device__ float g_agg0[(size_t)N0 * K];   // 16 MB hop-0 aggregates

__device__ __forceinline__ float warp_sum(float v) {
#pragma unroll
    for (int o = 16; o; o >>= 1) v += __shfl_xor_sync(0xffffffffu, v, o);
    return v;
}

// sum over a 16-lane group (xor offsets < 16 never cross the half-warp)
__device__ __forceinline__ float half_sum(float v) {
#pragma unroll
    for (int o = 8; o; o >>= 1) v += __shfl_xor_sync(0xffffffffu, v, o);
    return v;
}

// ---------------- hop 0: two nodes per warp, 16 lanes per node ----------------
__global__ void __launch_bounds__(256) hop0_kernel(
    const float* __restrict__ ent,
    const int*   __restrict__ node_ids0,
    const int*   __restrict__ nbr0)
{
    int halfwarp = (blockIdx.x * blockDim.x + threadIdx.x) >> 4;  // node id
    int l16      = threadIdx.x & 15;                              // lane in group
    int gbase    = threadIdx.x & 16;                              // 0 or 16
    if (halfwarp >= N0) return;

    // lane l holds neighbors 2l and 2l+1 of its node (coalesced int2 load)
    int2 myn = __ldg((const int2*)(nbr0 + halfwarp * DEG) + l16);

    // prefetch target row (independent of loop)
    int nid = __ldg(node_ids0 + halfwarp);
    float4 t = __ldg((const float4*)(ent + (size_t)nid * K) + l16);

    float s0 = 0.f, s1 = 0.f, s2 = 0.f, s3 = 0.f;
    float q0 = 0.f, q1 = 0.f, q2 = 0.f, q3 = 0.f;

#pragma unroll
    for (int base = 0; base < DEG; base += 4) {
        float4 v[4];
#pragma unroll
        for (int g = 0; g < 4; ++g) {
            int j = base + g;
            int idx = __shfl_sync(0xffffffffu, (j & 1) ? myn.y : myn.x,
                                  gbase + (j >> 1));
            v[g] = __ldg((const float4*)(ent + (size_t)idx * K) + l16);
        }
#pragma unroll
        for (int g = 0; g < 4; ++g) {
            float ss = half_sum(v[g].x * v[g].x + v[g].y * v[g].y +
                                v[g].z * v[g].z + v[g].w * v[g].w);
            float sc = ss > 1.f ? rsqrtf(ss) : 1.f;   // min(1, 1/||row||)
            float x0 = v[g].x * sc, x1 = v[g].y * sc,
                  x2 = v[g].z * sc, x3 = v[g].w * sc;
            s0 += x0; s1 += x1; s2 += x2; s3 += x3;
            q0 += x0 * x0; q1 += x1 * x1; q2 += x2 * x2; q3 += x3 * x3;
        }
    }

    float ts  = half_sum(t.x * t.x + t.y * t.y + t.z * t.z + t.w * t.w);
    float tsc = ts > 1.f ? rsqrtf(ts) : 1.f;

    float4 o;
    o.x = s0 * s0 - q0 + t.x * tsc;
    o.y = s1 * s1 - q1 + t.y * tsc;
    o.z = s2 * s2 - q2 + t.z * tsc;
    o.w = s3 * s3 - q3 + t.w * tsc;
    ((float4*)(g_agg0 + (size_t)halfwarp * K))[l16] = o;
}

// ---------------- hop 1: one block (4 warps) per batch item ----------------
__global__ void __launch_bounds__(128) hop1_kernel(
    const float* __restrict__ ent,
    const float* __restrict__ uemb,
    const int*   __restrict__ u,
    const int*   __restrict__ item_ids,
    const int*   __restrict__ nbr1,
    float*       __restrict__ out)
{
    __shared__ float4 part[4][32];

    int item = blockIdx.x;
    int w    = threadIdx.x >> 5;
    int lane = threadIdx.x & 31;

    int myn = 0;
    if (lane < 8) myn = __ldg(nbr1 + item * DEG + w * 8 + lane);

    float2 t = make_float2(0.f, 0.f), uv = make_float2(0.f, 0.f);
    if (w == 0) {
        int it = __ldg(item_ids + item);
        int uu = __ldg(u + item);
        t  = __ldg((const float2*)(ent  + (size_t)it * K) + lane);
        uv = __ldg((const float2*)(uemb + (size_t)uu * K) + lane);
    }

    float2 v[8];
#pragma unroll
    for (int g = 0; g < 8; ++g) {
        int idx = __shfl_sync(0xffffffffu, myn, g);
        v[g] = ((const float2*)(g_agg0 + (size_t)idx * K))[lane];
    }
    float s0 = 0.f, s1 = 0.f, q0 = 0.f, q1 = 0.f;
#pragma unroll
    for (int g = 0; g < 8; ++g) {
        s0 += v[g].x; s1 += v[g].y;
        q0 += v[g].x * v[g].x; q1 += v[g].y * v[g].y;
    }
    part[w][lane] = make_float4(s0, s1, q0, q1);
    __syncthreads();

    if (w == 0) {
        float4 a = part[0][lane], b = part[1][lane],
               c = part[2][lane], d = part[3][lane];
        float S0 = a.x + b.x + c.x + d.x;
        float S1 = a.y + b.y + c.y + d.y;
        float Q0 = a.z + b.z + c.z + d.z;
        float Q1 = a.w + b.w + c.w + d.w;

        float ts  = warp_sum(t.x * t.x + t.y * t.y);
        float tsc = ts > 1.f ? rsqrtf(ts) : 1.f;
        float i0 = S0 * S0 - Q0 + t.x * tsc;
        float i1 = S1 * S1 - Q1 + t.y * tsc;

        float us  = warp_sum(uv.x * uv.x + uv.y * uv.y);
        float usc = us > 1.f ? rsqrtf(us) : 1.f;

        float dot = warp_sum(uv.x * usc * i0 + uv.y * usc * i1);
        if (lane == 0) out[item] = 1.f / (1.f + expf(-dot));
    }
}

extern "C" void kernel_launch(void* const* d_in, const int* in_sizes, int n_in,
                              void* d_out, int out_size)
{
    const float* ent       = (const float*)d_in[0];
    const float* uemb      = (const float*)d_in[1];
    // d_in[2..5]: Wa, ba, Wh, bh — dead
    const int*   u         = (const int*)d_in[6];
    const int*   item_ids  = (const int*)d_in[7];
    const int*   nbr1      = (const int*)d_in[8];
    const int*   node_ids0 = (const int*)d_in[9];
    const int*   nbr0      = (const int*)d_in[10];
    float*       out       = (float*)d_out;

    // 2 nodes per warp -> 16 nodes per 256-thread block -> 4096 blocks
    hop0_kernel<<<N0 / 16, 256>>>(ent, node_ids0, nbr0);
    hop1_kernel<<<B, 128>>>(ent, uemb, u, item_ids, nbr1, out);
}